// round 7
// baseline (speedup 1.0000x reference)
#include <cuda_runtime.h>

#define EE 25
#define HH 37
#define NJ 6
#define CSTR 6                  // floats per cell, slots [w0,w3,w1,w4,w2,w5]
#define PEC 27                  // padded cols
#define ROWF (PEC * CSTR)       // 162 floats per padded row
#define PHR 41                  // padded rows: halo(0) + 39 band rows + guard(40)
#define NF (PHR * ROWF)         // 6642 floats per buffer
#define NTH 352
#define NBAND 13                // 13 bands x 3 rows = 39 rows (37,38 dead)
#define NACT (NBAND * EE)       // 325 active threads
#define GAMMA 0.9f
#define ADDC 12

// dr = {0,1,1,0,-1,-1} ; dc = {1,0,-1,-1,0,1}  packed (d+1), 2 bits per k
#define DR_PACK 105u
#define DC_PACK 2310u

#define SMEM_WORDS (2 * NF + HH + NJ * HH)
#define SMEM_BYTES (SMEM_WORDS * 4)

__device__ __forceinline__ float2 ld2(const float* p) { return *(const float2*)p; }

__global__ __launch_bounds__(NTH, 4) void vin_kernel(
    const float* __restrict__ goals,   // [B,6,25,25]
    const int*   __restrict__ state,   // [B,3]
    const float* __restrict__ obst,    // [B,25,25]
    const int*   __restrict__ n_iter,  // [1]
    float* __restrict__ out)           // [B,4]
{
    extern __shared__ float sm[];
    unsigned* obsh = (unsigned*)(sm + 2 * NF);   // [37]
    unsigned* gbsh = obsh + HH;                  // [6*37]

    const int b   = blockIdx.x;
    const int tid = threadIdx.x;

    // zero both buffers (incl. halos & guard rows)
    for (int i = tid; i < 2 * NF; i += NTH) sm[i] = 0.0f;

    // build bitmasks (t<37 -> obstacle row, else goal row per j)
    for (int t = tid; t < HH * (NJ + 1); t += NTH) {
        int r, j;
        if (t < HH) { r = t; j = -1; }
        else        { int tt = t - HH; j = tt / HH; r = tt - j * HH; }
        unsigned bits = 0u;
        #pragma unroll 1
        for (int c = 0; c < EE; ++c) {
            int u = r + (c >> 1) - ADDC;
            if (u >= 0 && u < EE) {
                if (j < 0) {
                    if (obst[(b * EE + u) * EE + c] == 0.0f) bits |= (1u << c);
                } else {
                    if (goals[((b * NJ + j) * EE + u) * EE + c] != 0.0f) bits |= (1u << c);
                }
            }
        }
        if (j < 0) obsh[r] = bits; else gbsh[t - HH] = bits;
    }
    __syncthreads();

    const bool active = (tid < NACT);
    int base = 0;
    float AmA = 0.f, AmB = 0.f, AmC = 0.f;
    unsigned cgA = 0u, cgB = 0u, cgC = 0u;
    float2 oA0={0,0}, oA1={0,0}, oA2={0,0};
    float2 oB0={0,0}, oB1={0,0}, oB2={0,0};
    float2 oC0={0,0}, oC1={0,0}, oC2={0,0};

    if (active) {
        int band = tid / EE;
        int c    = tid - band * EE;
        int rA   = 3 * band;
        base = (rA + 1) * ROWF + (c + 1) * CSTR;

        // per-row masks (rows >= 37 are dead: Am=0, cg=0)
        int rB = rA + 1, rC = rA + 2;
        unsigned obA = (obsh[rA] >> c) & 1u;
        unsigned obB = (rB < HH) ? ((obsh[rB] >> c) & 1u) : 0u;
        unsigned obC = (rC < HH) ? ((obsh[rC] >> c) & 1u) : 0u;
        AmA = obA ? GAMMA : 0.f;
        AmB = obB ? GAMMA : 0.f;
        AmC = obC ? GAMMA : 0.f;
        unsigned gA = 0u, gB = 0u, gC = 0u;
        int rBc = (rB < HH) ? rB : 0;
        int rCc = (rC < HH) ? rC : 0;
        #pragma unroll
        for (int j = 0; j < NJ; ++j) {
            gA |= ((gbsh[j * HH + rA ] >> c) & 1u) << j;
            gB |= ((gbsh[j * HH + rBc] >> c) & 1u) << j;
            gC |= ((gbsh[j * HH + rCc] >> c) & 1u) << j;
        }
        cgA = obA ? gA : 0u;
        cgB = obB ? gB : 0u;
        cgC = obC ? gC : 0u;

        oA0 = make_float2((cgA &  1u)?1.f:0.f, (cgA &  8u)?1.f:0.f);
        oA1 = make_float2((cgA &  2u)?1.f:0.f, (cgA & 16u)?1.f:0.f);
        oA2 = make_float2((cgA &  4u)?1.f:0.f, (cgA & 32u)?1.f:0.f);
        oB0 = make_float2((cgB &  1u)?1.f:0.f, (cgB &  8u)?1.f:0.f);
        oB1 = make_float2((cgB &  2u)?1.f:0.f, (cgB & 16u)?1.f:0.f);
        oB2 = make_float2((cgB &  4u)?1.f:0.f, (cgB & 32u)?1.f:0.f);
        oC0 = make_float2((cgC &  1u)?1.f:0.f, (cgC &  8u)?1.f:0.f);
        oC1 = make_float2((cgC &  2u)?1.f:0.f, (cgC & 16u)?1.f:0.f);
        oC2 = make_float2((cgC &  4u)?1.f:0.f, (cgC & 32u)?1.f:0.f);

        // seed sA = C
        *(float2*)(sm + base + 0) = oA0;
        *(float2*)(sm + base + 2) = oA1;
        *(float2*)(sm + base + 4) = oA2;
        *(float2*)(sm + base + ROWF + 0) = oB0;
        *(float2*)(sm + base + ROWF + 2) = oB1;
        *(float2*)(sm + base + ROWF + 4) = oB2;
        *(float2*)(sm + base + 2*ROWF + 0) = oC0;
        *(float2*)(sm + base + 2*ROWF + 2) = oC1;
        *(float2*)(sm + base + 2*ROWF + 4) = oC2;
    }
    __syncthreads();

    const int iters = n_iter[0];
    int spO = 0;

    for (int s = 0; s < iters; ++s) {
        if (active) {
            const float* SA = sm + spO + base;
            const float* SB = SA + ROWF;
            const float* SC = SB + ROWF;
            float*       DA = sm + (spO ^ NF) + base;

            // ---- batch all 14 independent loads up front (MLP) ----
            float2 a0 = ld2(SA + 6);
            float2 a2 = ld2(SA + 160);
            float2 a3 = ld2(SA - 6);
            float2 a4 = ld2(SA - 160);
            float2 a5 = ld2(SA - 152);
            float2 b0 = ld2(SB + 6);
            float2 b2 = ld2(SB + 160);
            float2 b3 = ld2(SB - 6);
            float2 b5 = ld2(SB - 152);
            float2 c0 = ld2(SC + 6);
            float2 c1 = ld2(SC + 164);
            float2 c2 = ld2(SC + 160);
            float2 c3 = ld2(SC - 6);
            float2 c5 = ld2(SC - 152);

            // row A (dir1 = oB1 register)
            float mA0 = fmaxf(fmaxf(a0.x, a3.x),  fmaxf(oA1.x, oA2.y));
            float mA1 = fmaxf(fmaxf(oB1.x, a4.x), fmaxf(oA2.x, oA0.x));
            float mA2 = fmaxf(fmaxf(a2.x, a5.x),  fmaxf(oA0.y, oA1.x));
            float mA3 = fmaxf(fmaxf(a3.y, a0.y),  fmaxf(oA1.y, oA2.x));
            float mA4 = fmaxf(fmaxf(a4.y, oB1.y), fmaxf(oA2.y, oA0.y));
            float mA5 = fmaxf(fmaxf(a5.y, a2.y),  fmaxf(oA0.x, oA1.y));
            // row B (dir1 = oC1, dir4 = oA1 registers)
            float mB0 = fmaxf(fmaxf(b0.x, b3.x),   fmaxf(oB1.x, oB2.y));
            float mB1 = fmaxf(fmaxf(oC1.x, oA1.x), fmaxf(oB2.x, oB0.x));
            float mB2 = fmaxf(fmaxf(b2.x, b5.x),   fmaxf(oB0.y, oB1.x));
            float mB3 = fmaxf(fmaxf(b3.y, b0.y),   fmaxf(oB1.y, oB2.x));
            float mB4 = fmaxf(fmaxf(oA1.y, oC1.y), fmaxf(oB2.y, oB0.y));
            float mB5 = fmaxf(fmaxf(b5.y, b2.y),   fmaxf(oB0.x, oB1.y));
            // row C (dir4 = oB1 register)
            float mC0 = fmaxf(fmaxf(c0.x, c3.x),  fmaxf(oC1.x, oC2.y));
            float mC1 = fmaxf(fmaxf(c1.x, oB1.x), fmaxf(oC2.x, oC0.x));
            float mC2 = fmaxf(fmaxf(c2.x, c5.x),  fmaxf(oC0.y, oC1.x));
            float mC3 = fmaxf(fmaxf(c3.y, c0.y),  fmaxf(oC1.y, oC2.x));
            float mC4 = fmaxf(fmaxf(oB1.y, c1.y), fmaxf(oC2.y, oC0.y));
            float mC5 = fmaxf(fmaxf(c5.y, c2.y),  fmaxf(oC0.x, oC1.y));

            oA0.x = fmaf(AmA, mA0, (cgA &  1u)?1.f:0.f);
            oA0.y = fmaf(AmA, mA3, (cgA &  8u)?1.f:0.f);
            oA1.x = fmaf(AmA, mA1, (cgA &  2u)?1.f:0.f);
            oA1.y = fmaf(AmA, mA4, (cgA & 16u)?1.f:0.f);
            oA2.x = fmaf(AmA, mA2, (cgA &  4u)?1.f:0.f);
            oA2.y = fmaf(AmA, mA5, (cgA & 32u)?1.f:0.f);
            oB0.x = fmaf(AmB, mB0, (cgB &  1u)?1.f:0.f);
            oB0.y = fmaf(AmB, mB3, (cgB &  8u)?1.f:0.f);
            oB1.x = fmaf(AmB, mB1, (cgB &  2u)?1.f:0.f);
            oB1.y = fmaf(AmB, mB4, (cgB & 16u)?1.f:0.f);
            oB2.x = fmaf(AmB, mB2, (cgB &  4u)?1.f:0.f);
            oB2.y = fmaf(AmB, mB5, (cgB & 32u)?1.f:0.f);
            oC0.x = fmaf(AmC, mC0, (cgC &  1u)?1.f:0.f);
            oC0.y = fmaf(AmC, mC3, (cgC &  8u)?1.f:0.f);
            oC1.x = fmaf(AmC, mC1, (cgC &  2u)?1.f:0.f);
            oC1.y = fmaf(AmC, mC4, (cgC & 16u)?1.f:0.f);
            oC2.x = fmaf(AmC, mC2, (cgC &  4u)?1.f:0.f);
            oC2.y = fmaf(AmC, mC5, (cgC & 32u)?1.f:0.f);

            float* DB = DA + ROWF;
            float* DC = DB + ROWF;
            *(float2*)(DA + 0) = oA0;
            *(float2*)(DA + 2) = oA1;
            *(float2*)(DA + 4) = oA2;
            *(float2*)(DB + 0) = oB0;
            *(float2*)(DB + 2) = oB1;
            *(float2*)(DB + 4) = oB2;
            *(float2*)(DC + 0) = oC0;
            *(float2*)(DC + 2) = oC1;
            *(float2*)(DC + 4) = oC2;
        }
        spO ^= NF;
        __syncthreads();
    }
    // sm + spO holds final s_plus = C + gamma*om*max(...)

    if (tid < 4) {
        int a     = tid;
        int alpha = state[b * 3 + 0];
        int u     = state[b * 3 + 1];
        int v     = state[b * 3 + 2];
        int rot   = (alpha + 1) % 6;
        int uu    = u - (v >> 1) + ADDC;

        int p, ddr = 0, ddc = 0;
        int drr = (int)((DR_PACK >> (2 * rot)) & 3u) - 1;
        int dcc = (int)((DC_PACK >> (2 * rot)) & 3u) - 1;
        if (a == 0)      { p = rot; ddr =  drr; ddc =  dcc; }
        else if (a == 1) { p = rot; ddr = -drr; ddc = -dcc; }
        else if (a == 2) { p = (rot + 1) % 6; }
        else             { p = (rot + 5) % 6; }

        float q = 0.0f;
        if ((obsh[uu] >> v) & 1u) {
            q = sm[spO + (uu + ddr + 1) * ROWF + (v + ddc + 1) * CSTR
                   + 2 * (p % 3) + (p / 3)];
        }
        out[b * 4 + a] = q;
    }
}

extern "C" void kernel_launch(void* const* d_in, const int* in_sizes, int n_in,
                              void* d_out, int out_size) {
    const float* goals  = (const float*)d_in[0];
    const int*   state  = (const int*)  d_in[1];
    const float* obst   = (const float*)d_in[2];
    const int*   n_iter = (const int*)  d_in[3];
    float* out = (float*)d_out;

    cudaFuncSetAttribute(vin_kernel,
                         cudaFuncAttributeMaxDynamicSharedMemorySize, SMEM_BYTES);

    int B = out_size / 4;   // 512
    vin_kernel<<<B, NTH, SMEM_BYTES>>>(goals, state, obst, n_iter, out);
}